// round 2
// baseline (speedup 1.0000x reference)
#include <cuda_runtime.h>
#include <cstdint>

// Problem constants (fixed by the dataset)
#define LQ_   256
#define HH_   2
#define HQ_   32
#define DD_   128
#define SS_   16
#define BS_   64
#define GG_   16
#define SM_SCALE 0.08838834764831845f   // 1/sqrt(128)

// Shared memory layout (float offsets). Row strides chosen so row stride
// (in bytes) is a multiple of 16 but NOT a multiple of 128 -> conflict-free
// ldmatrix row fetches.
#define QS_OFF   0
#define QS_STR   132                       // 16 rows  x 132
#define KS_OFF   (QS_OFF + 16*132)         // 2112
#define KS_STR   132                       // 64 rows  x 132
#define VT_OFF   (KS_OFF + 64*132)         // 10560
#define VT_STR   68                        // 128 rows x 68  (V transposed: [d][u])
#define PS_OFF   (VT_OFF + 128*68)         // 19264
#define PS_STR   68                        // 16 rows  x 68
#define WS_OFF   (PS_OFF + 16*68)          // 20352   (16x16 w coefs)
#define IDX_OFF  (WS_OFF + 256)            // 20608   (16 block indices, as int)
#define SMEM_FLOATS (IDX_OFF + 16)
#define SMEM_BYTES  (SMEM_FLOATS * 4)      // 82,496 B -> 2 CTAs/SM

__device__ __forceinline__ unsigned smem_u32(const void* p) {
    return (unsigned)__cvta_generic_to_shared(p);
}

__device__ __forceinline__ void ldsm_x4(unsigned& r0, unsigned& r1,
                                        unsigned& r2, unsigned& r3, unsigned addr) {
    asm volatile("ldmatrix.sync.aligned.m8n8.x4.shared.b16 {%0,%1,%2,%3}, [%4];"
                 : "=r"(r0), "=r"(r1), "=r"(r2), "=r"(r3) : "r"(addr));
}

__device__ __forceinline__ void ldsm_x2(unsigned& r0, unsigned& r1, unsigned addr) {
    asm volatile("ldmatrix.sync.aligned.m8n8.x2.shared.b16 {%0,%1}, [%2];"
                 : "=r"(r0), "=r"(r1) : "r"(addr));
}

__device__ __forceinline__ void mma_tf32(float c[4],
                                         unsigned a0, unsigned a1, unsigned a2, unsigned a3,
                                         unsigned b0, unsigned b1) {
    asm volatile("mma.sync.aligned.m16n8k8.row.col.f32.tf32.tf32.f32 "
                 "{%0,%1,%2,%3}, {%4,%5,%6,%7}, {%8,%9}, {%0,%1,%2,%3};"
                 : "+f"(c[0]), "+f"(c[1]), "+f"(c[2]), "+f"(c[3])
                 : "r"(a0), "r"(a1), "r"(a2), "r"(a3), "r"(b0), "r"(b1));
}

// Round-to-nearest tf32 "high" part; returns fp32 bit pattern with low 13
// mantissa bits zeroed (exactly representable in tf32).
__device__ __forceinline__ unsigned tf32_hi(unsigned x) {
    unsigned r;
    asm("cvt.rna.tf32.f32 %0, %1;" : "=r"(r) : "r"(x));
    return r;
}
__device__ __forceinline__ unsigned f_lo(unsigned x, unsigned hi) {
    return __float_as_uint(__fsub_rn(__uint_as_float(x), __uint_as_float(hi)));
}

// Split a 6-register fragment set (a0..a3, done by caller) helper for b pair
#define SPLIT1(x)  unsigned x##h = tf32_hi(x), x##l = f_lo(x, x##h)

__global__ void __launch_bounds__(128)
hsa_prefill_kernel(const float* __restrict__ q, const float* __restrict__ k,
                   const float* __restrict__ v, const float* __restrict__ w,
                   const int* __restrict__ bi, float* __restrict__ out)
{
    extern __shared__ float sm[];
    const int lq   = blockIdx.x;
    const int h    = blockIdx.y;
    const int tid  = threadIdx.x;
    const int warp = tid >> 5;
    const int lane = tid & 31;
    const int gID  = lane >> 2;   // 0..7
    const int tig  = lane & 3;    // 0..3

    // ---- Load Q tile [16][128], w coefs, indices
    {
        const float* qb = q + ((size_t)lq * HQ_ + (size_t)h * GG_) * DD_;
        #pragma unroll
        for (int i = tid; i < (GG_ * DD_) / 4; i += 128) {
            int idx = i * 4;
            int g = idx >> 7, d = idx & 127;
            float4 val = *(const float4*)(qb + idx);
            *(float4*)(sm + QS_OFF + g * QS_STR + d) = val;
        }
        const float* wb = w + ((size_t)lq * HQ_ + (size_t)h * GG_) * SS_;
        for (int i = tid; i < GG_ * SS_; i += 128) sm[WS_OFF + i] = wb[i];
        if (tid < SS_)
            ((int*)(sm + IDX_OFF))[tid] = bi[((size_t)lq * HH_ + h) * SS_ + tid];
    }
    __syncthreads();

    // Persistent O accumulators: warp owns d-range [warp*32, warp*32+32)
    float oacc[4][4];
    #pragma unroll
    for (int i = 0; i < 4; i++)
        #pragma unroll
        for (int j = 0; j < 4; j++) oacc[i][j] = 0.f;

    // ldmatrix lane-address components
    const int lr = lane & 7;
    const int lt = lane >> 3;
    const int a_row = lr + ((lt & 1) << 3);   // x4 A pattern rows
    const int a_col = (lt >> 1) << 2;         // x4 A pattern col offset (0 or 4)
    const int b_t   = lt & 1;                 // x2 B pattern

    for (int s = 0; s < SS_; s++) {
        const int blk = ((const int*)(sm + IDX_OFF))[s];
        if (blk < 0) continue;   // uniform across CTA -> safe with barriers

        // ---- Gather K block -> ks[u][d], V block (transposed) -> vts[d][u]
        {
            const int u    = tid >> 1;
            const int half = (tid & 1) << 6;
            const size_t rowoff = ((size_t)(blk * BS_ + u) * HH_ + h) * DD_ + half;
            const float* krow = k + rowoff;
            const float* vrow = v + rowoff;
            float* kd = sm + KS_OFF + u * KS_STR + half;
            #pragma unroll
            for (int j = 0; j < 16; j++) {
                float4 kv = *(const float4*)(krow + j * 4);
                *(float4*)(kd + j * 4) = kv;
                float4 vv = *(const float4*)(vrow + j * 4);
                const int d = half + j * 4;
                sm[VT_OFF + (d + 0) * VT_STR + u] = vv.x;
                sm[VT_OFF + (d + 1) * VT_STR + u] = vv.y;
                sm[VT_OFF + (d + 2) * VT_STR + u] = vv.z;
                sm[VT_OFF + (d + 3) * VT_STR + u] = vv.w;
            }
        }
        __syncthreads();

        // ---- Scores S[16][64] = Q @ K^T (3xTF32). Warp covers u-tiles {2w,2w+1}.
        float c[2][4] = {{0.f,0.f,0.f,0.f},{0.f,0.f,0.f,0.f}};
        #pragma unroll
        for (int kt = 0; kt < 16; kt++) {
            unsigned a0, a1, a2, a3;
            ldsm_x4(a0, a1, a2, a3,
                    smem_u32(sm + QS_OFF + a_row * QS_STR + a_col + kt * 8));
            SPLIT1(a0); SPLIT1(a1); SPLIT1(a2); SPLIT1(a3);
            #pragma unroll
            for (int nt = 0; nt < 2; nt++) {
                const int u0 = (warp * 2 + nt) * 8;
                unsigned b0, b1;
                ldsm_x2(b0, b1,
                        smem_u32(sm + KS_OFF + (u0 + lr) * KS_STR + kt * 8 + b_t * 4));
                SPLIT1(b0); SPLIT1(b1);
                mma_tf32(c[nt], a0h, a1h, a2h, a3h, b0h, b1h);
                mma_tf32(c[nt], a0h, a1h, a2h, a3h, b0l, b1l);
                mma_tf32(c[nt], a0l, a1l, a2l, a3l, b0h, b1h);
            }
        }
        // Spill scaled scores to smem for the cross-warp softmax
        #pragma unroll
        for (int nt = 0; nt < 2; nt++) {
            const int u = (warp * 2 + nt) * 8 + tig * 2;
            *(float2*)(sm + PS_OFF + gID * PS_STR + u) =
                make_float2(c[nt][0] * SM_SCALE, c[nt][1] * SM_SCALE);
            *(float2*)(sm + PS_OFF + (gID + 8) * PS_STR + u) =
                make_float2(c[nt][2] * SM_SCALE, c[nt][3] * SM_SCALE);
        }
        __syncthreads();

        // ---- Per-(g, block) softmax over 64 keys; fold in w[g][s]/sum.
        {
            const int g = tid >> 3, j = tid & 7;   // 8 threads per row
            float vals[8];
            #pragma unroll
            for (int m = 0; m < 8; m++) vals[m] = sm[PS_OFF + g * PS_STR + j + m * 8];
            float mx = vals[0];
            #pragma unroll
            for (int m = 1; m < 8; m++) mx = fmaxf(mx, vals[m]);
            mx = fmaxf(mx, __shfl_xor_sync(0xffffffffu, mx, 1));
            mx = fmaxf(mx, __shfl_xor_sync(0xffffffffu, mx, 2));
            mx = fmaxf(mx, __shfl_xor_sync(0xffffffffu, mx, 4));
            float sum = 0.f;
            #pragma unroll
            for (int m = 0; m < 8; m++) { vals[m] = __expf(vals[m] - mx); sum += vals[m]; }
            sum += __shfl_xor_sync(0xffffffffu, sum, 1);
            sum += __shfl_xor_sync(0xffffffffu, sum, 2);
            sum += __shfl_xor_sync(0xffffffffu, sum, 4);
            const float coef = sm[WS_OFF + g * SS_ + s] / sum;
            #pragma unroll
            for (int m = 0; m < 8; m++)
                sm[PS_OFF + g * PS_STR + j + m * 8] = vals[m] * coef;
        }
        __syncthreads();

        // ---- O[16][128] += P[16][64] @ V[64][128] (3xTF32). Warp: d-tiles {4w..4w+3}.
        #pragma unroll
        for (int kt = 0; kt < 8; kt++) {
            unsigned a0, a1, a2, a3;
            ldsm_x4(a0, a1, a2, a3,
                    smem_u32(sm + PS_OFF + a_row * PS_STR + a_col + kt * 8));
            SPLIT1(a0); SPLIT1(a1); SPLIT1(a2); SPLIT1(a3);
            #pragma unroll
            for (int nt = 0; nt < 4; nt++) {
                const int d0 = warp * 32 + nt * 8;
                unsigned b0, b1;
                ldsm_x2(b0, b1,
                        smem_u32(sm + VT_OFF + (d0 + lr) * VT_STR + kt * 8 + b_t * 4));
                SPLIT1(b0); SPLIT1(b1);
                mma_tf32(oacc[nt], a0h, a1h, a2h, a3h, b0h, b1h);
                mma_tf32(oacc[nt], a0h, a1h, a2h, a3h, b0l, b1l);
                mma_tf32(oacc[nt], a0l, a1l, a2l, a3l, b0h, b1h);
            }
        }
        __syncthreads();   // protect ks/vts/ps before next iteration's fills
    }

    // ---- Write O: warp's d-slice, fragment layout rows gID / gID+8.
    float* ob = out + ((size_t)lq * HQ_ + (size_t)h * GG_) * DD_;
    #pragma unroll
    for (int nt = 0; nt < 4; nt++) {
        const int d = warp * 32 + nt * 8 + tig * 2;
        *(float2*)(ob + (size_t)gID * DD_ + d)       = make_float2(oacc[nt][0], oacc[nt][1]);
        *(float2*)(ob + (size_t)(gID + 8) * DD_ + d) = make_float2(oacc[nt][2], oacc[nt][3]);
    }
}

extern "C" void kernel_launch(void* const* d_in, const int* in_sizes, int n_in,
                              void* d_out, int out_size)
{
    const float* q  = (const float*)d_in[0];
    const float* k  = (const float*)d_in[1];
    const float* v  = (const float*)d_in[2];
    const float* w  = (const float*)d_in[3];
    const int*   bi = (const int*)d_in[4];
    float* out = (float*)d_out;

    cudaFuncSetAttribute(hsa_prefill_kernel,
                         cudaFuncAttributeMaxDynamicSharedMemorySize, SMEM_BYTES);
    hsa_prefill_kernel<<<dim3(LQ_, HH_), 128, SMEM_BYTES>>>(q, k, v, w, bi, out);
}

// round 3
// speedup vs baseline: 2.1138x; 2.1138x over previous
#include <cuda_runtime.h>
#include <cstdint>

// Problem constants (fixed by the dataset)
#define LQ_   256
#define HH_   2
#define HQ_   32
#define DD_   128
#define SS_   16
#define BS_   64
#define GG_   16
#define SM_SCALE 0.08838834764831845f   // 1/sqrt(128)

// Shared memory: only Q, P, w, indices. Row strides chosen so row pitch is a
// multiple of 16B but not of 128B -> conflict-free ldmatrix row fetches.
#define QS_OFF   0
#define QS_STR   132                       // 16 rows x 132
#define PS_OFF   (QS_OFF + 16*132)         // 2112
#define PS_STR   68                        // 16 rows x 68
#define WS_OFF   (PS_OFF + 16*68)          // 3200
#define IDX_OFF  (WS_OFF + 256)            // 3456
#define SMEM_FLOATS (IDX_OFF + 16)
#define SMEM_BYTES  (SMEM_FLOATS * 4)      // 13,888 B -> 4+ CTAs/SM

__device__ __forceinline__ unsigned smem_u32(const void* p) {
    return (unsigned)__cvta_generic_to_shared(p);
}

__device__ __forceinline__ void ldsm_x4(unsigned& r0, unsigned& r1,
                                        unsigned& r2, unsigned& r3, unsigned addr) {
    asm volatile("ldmatrix.sync.aligned.m8n8.x4.shared.b16 {%0,%1,%2,%3}, [%4];"
                 : "=r"(r0), "=r"(r1), "=r"(r2), "=r"(r3) : "r"(addr));
}

__device__ __forceinline__ void mma_tf32(float c[4],
                                         unsigned a0, unsigned a1, unsigned a2, unsigned a3,
                                         unsigned b0, unsigned b1) {
    asm volatile("mma.sync.aligned.m16n8k8.row.col.f32.tf32.tf32.f32 "
                 "{%0,%1,%2,%3}, {%4,%5,%6,%7}, {%8,%9}, {%0,%1,%2,%3};"
                 : "+f"(c[0]), "+f"(c[1]), "+f"(c[2]), "+f"(c[3])
                 : "r"(a0), "r"(a1), "r"(a2), "r"(a3), "r"(b0), "r"(b1));
}

// Round-to-nearest tf32 "high" part (low 13 mantissa bits zeroed).
__device__ __forceinline__ unsigned tf32_hi(unsigned x) {
    unsigned r;
    asm("cvt.rna.tf32.f32 %0, %1;" : "=r"(r) : "r"(x));
    return r;
}
__device__ __forceinline__ unsigned f_lo(unsigned x, unsigned hi) {
    return __float_as_uint(__fsub_rn(__uint_as_float(x), __uint_as_float(hi)));
}
#define SPLIT1(x)  unsigned x##h = tf32_hi(x), x##l = f_lo(x, x##h)
#define SPLITF(x)  unsigned x##h = tf32_hi(__float_as_uint(x)), \
                            x##l = f_lo(__float_as_uint(x), x##h)

__global__ void __launch_bounds__(128, 4)
hsa_prefill_kernel(const float* __restrict__ q, const float* __restrict__ k,
                   const float* __restrict__ v, const float* __restrict__ w,
                   const int* __restrict__ bi, float* __restrict__ out)
{
    extern __shared__ float sm[];
    const int lq   = blockIdx.x;
    const int h    = blockIdx.y;
    const int tid  = threadIdx.x;
    const int warp = tid >> 5;
    const int lane = tid & 31;
    const int gID  = lane >> 2;   // 0..7
    const int tig  = lane & 3;    // 0..3

    // ---- Load Q tile [16][128], w coefs, block indices
    {
        const float* qb = q + ((size_t)lq * HQ_ + (size_t)h * GG_) * DD_;
        #pragma unroll
        for (int i = tid; i < (GG_ * DD_) / 4; i += 128) {
            int idx = i * 4;
            int g = idx >> 7, d = idx & 127;
            float4 val = *(const float4*)(qb + idx);
            *(float4*)(sm + QS_OFF + g * QS_STR + d) = val;
        }
        const float* wb = w + ((size_t)lq * HQ_ + (size_t)h * GG_) * SS_;
        for (int i = tid; i < GG_ * SS_; i += 128) sm[WS_OFF + i] = wb[i];
        if (tid < SS_)
            ((int*)(sm + IDX_OFF))[tid] = bi[((size_t)lq * HH_ + h) * SS_ + tid];
    }
    __syncthreads();

    // Persistent O accumulators (hi and correction kept separate -> 2x ILP)
    float oh[4][4], oc[4][4];
    #pragma unroll
    for (int i = 0; i < 4; i++)
        #pragma unroll
        for (int j = 0; j < 4; j++) { oh[i][j] = 0.f; oc[i][j] = 0.f; }

    // ldmatrix A-fragment address components
    const int lr = lane & 7;
    const int lt = lane >> 3;
    const int a_row = lr + ((lt & 1) << 3);
    const int a_col = (lt >> 1) << 2;

    for (int s = 0; s < SS_; s++) {
        const int blk = ((const int*)(sm + IDX_OFF))[s];   // uniform across CTA
        if (blk >= 0) {
            const size_t base = ((size_t)blk * BS_ * HH_ + h) * DD_;  // block row 0
            // K rows for this warp's two n-tiles: u0 = warp*16 (+8)
            const float* kr0 = k + base + (size_t)(warp * 16 + gID) * (HH_ * DD_);
            const float* kr1 = kr0 + 8 * (HH_ * DD_);
            // V base for PV: row u = tig, col warp*32 + gID
            const float* vb = v + base + (size_t)tig * (HH_ * DD_) + warp * 32 + gID;

            // ---- Scores S[16][64] = Q @ K^T (3xTF32, split accumulators)
            float cm[2][4] = {{0.f,0.f,0.f,0.f},{0.f,0.f,0.f,0.f}};
            float cc[2][4] = {{0.f,0.f,0.f,0.f},{0.f,0.f,0.f,0.f}};
            #pragma unroll
            for (int kt = 0; kt < 16; kt++) {
                unsigned a0, a1, a2, a3;
                ldsm_x4(a0, a1, a2, a3,
                        smem_u32(sm + QS_OFF + a_row * QS_STR + a_col + kt * 8));
                SPLIT1(a0); SPLIT1(a1); SPLIT1(a2); SPLIT1(a3);
                float f0 = kr0[kt * 8 + tig], f1 = kr0[kt * 8 + tig + 4];
                float f2 = kr1[kt * 8 + tig], f3 = kr1[kt * 8 + tig + 4];
                SPLITF(f0); SPLITF(f1); SPLITF(f2); SPLITF(f3);
                mma_tf32(cm[0], a0h, a1h, a2h, a3h, f0h, f1h);
                mma_tf32(cc[0], a0h, a1h, a2h, a3h, f0l, f1l);
                mma_tf32(cc[0], a0l, a1l, a2l, a3l, f0h, f1h);
                mma_tf32(cm[1], a0h, a1h, a2h, a3h, f2h, f3h);
                mma_tf32(cc[1], a0h, a1h, a2h, a3h, f2l, f3l);
                mma_tf32(cc[1], a0l, a1l, a2l, a3l, f2h, f3h);
            }
            // Spill scaled scores for the cross-warp softmax
            #pragma unroll
            for (int nt = 0; nt < 2; nt++) {
                const int u = (warp * 2 + nt) * 8 + tig * 2;
                *(float2*)(sm + PS_OFF + gID * PS_STR + u) =
                    make_float2((cm[nt][0] + cc[nt][0]) * SM_SCALE,
                                (cm[nt][1] + cc[nt][1]) * SM_SCALE);
                *(float2*)(sm + PS_OFF + (gID + 8) * PS_STR + u) =
                    make_float2((cm[nt][2] + cc[nt][2]) * SM_SCALE,
                                (cm[nt][3] + cc[nt][3]) * SM_SCALE);
            }
            __syncthreads();

            // ---- Per-(g, block) softmax over 64 keys; fold in w[g][s]/sum.
            {
                const int g = tid >> 3, j = tid & 7;   // 8 threads per row
                float vals[8];
                #pragma unroll
                for (int m = 0; m < 8; m++) vals[m] = sm[PS_OFF + g * PS_STR + j + m * 8];
                float mx = vals[0];
                #pragma unroll
                for (int m = 1; m < 8; m++) mx = fmaxf(mx, vals[m]);
                mx = fmaxf(mx, __shfl_xor_sync(0xffffffffu, mx, 1));
                mx = fmaxf(mx, __shfl_xor_sync(0xffffffffu, mx, 2));
                mx = fmaxf(mx, __shfl_xor_sync(0xffffffffu, mx, 4));
                float sum = 0.f;
                #pragma unroll
                for (int m = 0; m < 8; m++) { vals[m] = __expf(vals[m] - mx); sum += vals[m]; }
                sum += __shfl_xor_sync(0xffffffffu, sum, 1);
                sum += __shfl_xor_sync(0xffffffffu, sum, 2);
                sum += __shfl_xor_sync(0xffffffffu, sum, 4);
                const float coef = sm[WS_OFF + g * SS_ + s] / sum;
                #pragma unroll
                for (int m = 0; m < 8; m++)
                    sm[PS_OFF + g * PS_STR + j + m * 8] = vals[m] * coef;
            }
            __syncthreads();

            // ---- O[16][128] += P[16][64] @ V[64][128] (3xTF32, V from gmem)
            #pragma unroll
            for (int kt = 0; kt < 8; kt++) {
                unsigned a0, a1, a2, a3;
                ldsm_x4(a0, a1, a2, a3,
                        smem_u32(sm + PS_OFF + a_row * PS_STR + a_col + kt * 8));
                SPLIT1(a0); SPLIT1(a1); SPLIT1(a2); SPLIT1(a3);
                #pragma unroll
                for (int nt = 0; nt < 4; nt++) {
                    float f0 = vb[(size_t)kt * 8 * (HH_ * DD_) + nt * 8];
                    float f1 = vb[(size_t)(kt * 8 + 4) * (HH_ * DD_) + nt * 8];
                    SPLITF(f0); SPLITF(f1);
                    mma_tf32(oh[nt], a0h, a1h, a2h, a3h, f0h, f1h);
                    mma_tf32(oc[nt], a0h, a1h, a2h, a3h, f0l, f1l);
                    mma_tf32(oc[nt], a0l, a1l, a2l, a3l, f0h, f1h);
                }
            }
            __syncthreads();   // protect PS before next iteration's spill
        }
    }

    // ---- Write O: warp's d-slice, fragment rows gID / gID+8.
    float* ob = out + ((size_t)lq * HQ_ + (size_t)h * GG_) * DD_;
    #pragma unroll
    for (int nt = 0; nt < 4; nt++) {
        const int d = warp * 32 + nt * 8 + tig * 2;
        *(float2*)(ob + (size_t)gID * DD_ + d) =
            make_float2(oh[nt][0] + oc[nt][0], oh[nt][1] + oc[nt][1]);
        *(float2*)(ob + (size_t)(gID + 8) * DD_ + d) =
            make_float2(oh[nt][2] + oc[nt][2], oh[nt][3] + oc[nt][3]);
    }
}

extern "C" void kernel_launch(void* const* d_in, const int* in_sizes, int n_in,
                              void* d_out, int out_size)
{
    const float* q  = (const float*)d_in[0];
    const float* k  = (const float*)d_in[1];
    const float* v  = (const float*)d_in[2];
    const float* w  = (const float*)d_in[3];
    const int*   bi = (const int*)d_in[4];
    float* out = (float*)d_out;

    cudaFuncSetAttribute(hsa_prefill_kernel,
                         cudaFuncAttributeMaxDynamicSharedMemorySize, SMEM_BYTES);
    hsa_prefill_kernel<<<dim3(LQ_, HH_), 128, SMEM_BYTES>>>(q, k, v, w, bi, out);
}

// round 5
// speedup vs baseline: 2.6265x; 1.2425x over previous
#include <cuda_runtime.h>
#include <cstdint>

// Problem constants (fixed by the dataset)
#define LQ_   256
#define HH_   2
#define HQ_   32
#define DD_   128
#define SS_   16
#define BS_   64
#define GG_   16
#define SM_SCALE 0.08838834764831845f   // 1/sqrt(128)

// Shared memory (float offsets)
#define QS_OFF   0
#define QS_STR   132                       // 16 rows x 132 (pitch !≡ 0 mod 128B)
#define PS_OFF   (QS_OFF + 16*132)         // 2112
#define PS_STR   68                        // 16 rows x 68
#define WS_OFF   (PS_OFF + 16*68)          // 3200
#define IDX_OFF  (WS_OFF + 256)            // 3456
#define KS_OFF   3584                      // 1024B-aligned; swizzled K tile
#define SMEM_FLOATS (KS_OFF + 64*128)      // 11776
#define SMEM_BYTES  (SMEM_FLOATS * 4)      // 47,104 B -> 4 CTAs/SM

__device__ __forceinline__ unsigned smem_u32(const void* p) {
    return (unsigned)__cvta_generic_to_shared(p);
}

__device__ __forceinline__ void ldsm_x4(unsigned& r0, unsigned& r1,
                                        unsigned& r2, unsigned& r3, unsigned addr) {
    asm volatile("ldmatrix.sync.aligned.m8n8.x4.shared.b16 {%0,%1,%2,%3}, [%4];"
                 : "=r"(r0), "=r"(r1), "=r"(r2), "=r"(r3) : "r"(addr));
}

__device__ __forceinline__ void ldsm_x2(unsigned& r0, unsigned& r1, unsigned addr) {
    asm volatile("ldmatrix.sync.aligned.m8n8.x2.shared.b16 {%0,%1}, [%2];"
                 : "=r"(r0), "=r"(r1) : "r"(addr));
}

__device__ __forceinline__ void mma_tf32(float c[4],
                                         unsigned a0, unsigned a1, unsigned a2, unsigned a3,
                                         unsigned b0, unsigned b1) {
    asm volatile("mma.sync.aligned.m16n8k8.row.col.f32.tf32.tf32.f32 "
                 "{%0,%1,%2,%3}, {%4,%5,%6,%7}, {%8,%9}, {%0,%1,%2,%3};"
                 : "+f"(c[0]), "+f"(c[1]), "+f"(c[2]), "+f"(c[3])
                 : "r"(a0), "r"(a1), "r"(a2), "r"(a3), "r"(b0), "r"(b1));
}

__device__ __forceinline__ unsigned tf32_hi(unsigned x) {
    unsigned r;
    asm("cvt.rna.tf32.f32 %0, %1;" : "=r"(r) : "r"(x));
    return r;
}
__device__ __forceinline__ unsigned f_lo(unsigned x, unsigned hi) {
    return __float_as_uint(__fsub_rn(__uint_as_float(x), __uint_as_float(hi)));
}
#define SPLIT1(x)  unsigned x##h = tf32_hi(x), x##l = f_lo(x, x##h)
#define SPLITF(x)  unsigned x##h = tf32_hi(__float_as_uint(x)), \
                            x##l = f_lo(__float_as_uint(x), x##h)

// Coalesced, swizzled K-tile prefetch: warp w loads rows [w*16, w*16+16),
// one full 512B row per warp-instruction (lane = 16B chunk).
__device__ __forceinline__ void prefetch_k(const float* kbase, unsigned ks_u32,
                                           int warp, int lane) {
    #pragma unroll
    for (int j = 0; j < 16; j++) {
        const int u = warp * 16 + j;
        const float* src = kbase + (size_t)u * (HH_ * DD_) + lane * 4;
        unsigned dst = ks_u32 + u * 512 + ((((unsigned)lane) ^ (u & 7)) << 4);
        asm volatile("cp.async.cg.shared.global [%0], [%1], 16;"
                     :: "r"(dst), "l"(src));
    }
}

__global__ void __launch_bounds__(128, 4)
hsa_prefill_kernel(const float* __restrict__ q, const float* __restrict__ k,
                   const float* __restrict__ v, const float* __restrict__ w,
                   const int* __restrict__ bi, float* __restrict__ out)
{
    extern __shared__ float sm[];
    const int lq   = blockIdx.x;
    const int h    = blockIdx.y;
    const int tid  = threadIdx.x;
    const int warp = tid >> 5;
    const int lane = tid & 31;
    const int gID  = lane >> 2;   // 0..7
    const int tig  = lane & 3;    // 0..3

    const unsigned ks_u32 = smem_u32(sm + KS_OFF);
    const int* bi_row = bi + ((size_t)lq * HH_ + h) * SS_;

    // ---- Kick off K(0) prefetch immediately (overlaps Q/w/idx loads)
    {
        int blk0 = bi_row[0]; if (blk0 < 0) blk0 = 0;
        const float* kb = k + ((size_t)blk0 * BS_ * HH_ + h) * DD_;
        prefetch_k(kb, ks_u32, warp, lane);
        asm volatile("cp.async.commit_group;");
    }

    // ---- Load Q tile [16][128], w coefs, block indices
    {
        const float* qb = q + ((size_t)lq * HQ_ + (size_t)h * GG_) * DD_;
        #pragma unroll
        for (int i = tid; i < (GG_ * DD_) / 4; i += 128) {
            int idx = i * 4;
            int g = idx >> 7, d = idx & 127;
            float4 val = *(const float4*)(qb + idx);
            *(float4*)(sm + QS_OFF + g * QS_STR + d) = val;
        }
        const float* wb = w + ((size_t)lq * HQ_ + (size_t)h * GG_) * SS_;
        for (int i = tid; i < GG_ * SS_; i += 128) sm[WS_OFF + i] = wb[i];
        if (tid < SS_) ((int*)(sm + IDX_OFF))[tid] = bi_row[tid];
    }

    // Persistent O accumulators (hi + correction kept separate -> 2x ILP)
    float oh[4][4], oc[4][4];
    #pragma unroll
    for (int i = 0; i < 4; i++)
        #pragma unroll
        for (int j = 0; j < 4; j++) { oh[i][j] = 0.f; oc[i][j] = 0.f; }

    // ldmatrix lane-address components
    const int lr = lane & 7;
    const int lt = lane >> 3;
    const int a_row = lr + ((lt & 1) << 3);
    const int a_col = (lt >> 1) << 2;
    const int b_t   = lt & 1;
    // K-frag swizzled row bases for this warp's two n-tiles (u0 = warp*16, +8)
    const unsigned krow0 = ks_u32 + (warp * 16 + lr) * 512;
    const unsigned krow1 = krow0 + 8 * 512;

    for (int s = 0; s < SS_; s++) {
        // K(s) in flight -> drain; barrier also orders Q/idx (s=0) and
        // P(s-1) consumption before this iteration's spill.
        asm volatile("cp.async.wait_group 0;" ::: "memory");
        __syncthreads();

        const int blk = ((const int*)(sm + IDX_OFF))[s];   // uniform across CTA

        float cm[2][4] = {{0.f,0.f,0.f,0.f},{0.f,0.f,0.f,0.f}};
        float cc[2][4] = {{0.f,0.f,0.f,0.f},{0.f,0.f,0.f,0.f}};
        if (blk >= 0) {
            // ---- Scores S[16][64] = Q @ K^T (3xTF32), K from swizzled smem
            #pragma unroll
            for (int kt = 0; kt < 16; kt++) {
                unsigned a0, a1, a2, a3;
                ldsm_x4(a0, a1, a2, a3,
                        smem_u32(sm + QS_OFF + a_row * QS_STR + a_col + kt * 8));
                SPLIT1(a0); SPLIT1(a1); SPLIT1(a2); SPLIT1(a3);
                const unsigned csw = ((unsigned)(kt * 2 + b_t) ^ lr) << 4;
                unsigned b0, b1, b2, b3;
                ldsm_x2(b0, b1, krow0 + csw);
                ldsm_x2(b2, b3, krow1 + csw);
                SPLIT1(b0); SPLIT1(b1); SPLIT1(b2); SPLIT1(b3);
                mma_tf32(cm[0], a0h, a1h, a2h, a3h, b0h, b1h);
                mma_tf32(cc[0], a0h, a1h, a2h, a3h, b0l, b1l);
                mma_tf32(cc[0], a0l, a1l, a2l, a3l, b0h, b1h);
                mma_tf32(cm[1], a0h, a1h, a2h, a3h, b2h, b3h);
                mma_tf32(cc[1], a0h, a1h, a2h, a3h, b2l, b3l);
                mma_tf32(cc[1], a0l, a1l, a2l, a3l, b2h, b3h);
            }
            // Spill scaled scores for the cross-warp softmax
            #pragma unroll
            for (int nt = 0; nt < 2; nt++) {
                const int u = (warp * 2 + nt) * 8 + tig * 2;
                *(float2*)(sm + PS_OFF + gID * PS_STR + u) =
                    make_float2((cm[nt][0] + cc[nt][0]) * SM_SCALE,
                                (cm[nt][1] + cc[nt][1]) * SM_SCALE);
                *(float2*)(sm + PS_OFF + (gID + 8) * PS_STR + u) =
                    make_float2((cm[nt][2] + cc[nt][2]) * SM_SCALE,
                                (cm[nt][3] + cc[nt][3]) * SM_SCALE);
            }
        }
        __syncthreads();   // all QK reads of K(s) done; P spilled

        // ---- Prefetch K(s+1) overlapped with softmax + PV
        if (s + 1 < SS_) {
            int nblk = ((const int*)(sm + IDX_OFF))[s + 1]; if (nblk < 0) nblk = 0;
            const float* kb = k + ((size_t)nblk * BS_ * HH_ + h) * DD_;
            prefetch_k(kb, ks_u32, warp, lane);
        }
        asm volatile("cp.async.commit_group;");

        if (blk >= 0) {
            // ---- Per-(g, block) softmax over 64 keys; fold in w[g][s]/sum.
            {
                const int g = tid >> 3, j = tid & 7;
                float vals[8];
                #pragma unroll
                for (int m = 0; m < 8; m++) vals[m] = sm[PS_OFF + g * PS_STR + j + m * 8];
                float mx = vals[0];
                #pragma unroll
                for (int m = 1; m < 8; m++) mx = fmaxf(mx, vals[m]);
                mx = fmaxf(mx, __shfl_xor_sync(0xffffffffu, mx, 1));
                mx = fmaxf(mx, __shfl_xor_sync(0xffffffffu, mx, 2));
                mx = fmaxf(mx, __shfl_xor_sync(0xffffffffu, mx, 4));
                float sum = 0.f;
                #pragma unroll
                for (int m = 0; m < 8; m++) { vals[m] = __expf(vals[m] - mx); sum += vals[m]; }
                sum += __shfl_xor_sync(0xffffffffu, sum, 1);
                sum += __shfl_xor_sync(0xffffffffu, sum, 2);
                sum += __shfl_xor_sync(0xffffffffu, sum, 4);
                const float coef = sm[WS_OFF + g * SS_ + s] / sum;
                #pragma unroll
                for (int m = 0; m < 8; m++)
                    sm[PS_OFF + g * PS_STR + j + m * 8] = vals[m] * coef;
            }
            __syncthreads();

            // ---- O += P[16][64] @ V[64][128] (3xTF32, V direct from L2)
            const float* vb = v + ((size_t)blk * BS_ * HH_ + h) * DD_
                            + (size_t)tig * (HH_ * DD_) + warp * 32 + gID;
            #pragma unroll
            for (int kt = 0; kt < 8; kt++) {
                unsigned a0, a1, a2, a3;
                ldsm_x4(a0, a1, a2, a3,
                        smem_u32(sm + PS_OFF + a_row * PS_STR + a_col + kt * 8));
                SPLIT1(a0); SPLIT1(a1); SPLIT1(a2); SPLIT1(a3);
                #pragma unroll
                for (int nt = 0; nt < 4; nt++) {
                    float f0 = vb[(size_t)kt * 8 * (HH_ * DD_) + nt * 8];
                    float f1 = vb[(size_t)(kt * 8 + 4) * (HH_ * DD_) + nt * 8];
                    SPLITF(f0); SPLITF(f1);
                    mma_tf32(oh[nt], a0h, a1h, a2h, a3h, f0h, f1h);
                    mma_tf32(oc[nt], a0h, a1h, a2h, a3h, f0l, f1l);
                    mma_tf32(oc[nt], a0l, a1l, a2l, a3l, f0h, f1h);
                }
            }
        }
    }

    // ---- Write O: warp's d-slice, fragment rows gID / gID+8.
    float* ob = out + ((size_t)lq * HQ_ + (size_t)h * GG_) * DD_;
    #pragma unroll
    for (int nt = 0; nt < 4; nt++) {
        const int d = warp * 32 + nt * 8 + tig * 2;
        *(float2*)(ob + (size_t)gID * DD_ + d) =
            make_float2(oh[nt][0] + oc[nt][0], oh[nt][1] + oc[nt][1]);
        *(float2*)(ob + (size_t)(gID + 8) * DD_ + d) =
            make_float2(oh[nt][2] + oc[nt][2], oh[nt][3] + oc[nt][3]);
    }
}

extern "C" void kernel_launch(void* const* d_in, const int* in_sizes, int n_in,
                              void* d_out, int out_size)
{
    const float* q  = (const float*)d_in[0];
    const float* k  = (const float*)d_in[1];
    const float* v  = (const float*)d_in[2];
    const float* w  = (const float*)d_in[3];
    const int*   bi = (const int*)d_in[4];
    float* out = (float*)d_out;

    cudaFuncSetAttribute(hsa_prefill_kernel,
                         cudaFuncAttributeMaxDynamicSharedMemorySize, SMEM_BYTES);
    hsa_prefill_kernel<<<dim3(LQ_, HH_), 128, SMEM_BYTES>>>(q, k, v, w, bi, out);
}

// round 6
// speedup vs baseline: 2.6336x; 1.0027x over previous
#include <cuda_runtime.h>
#include <cstdint>

// Problem constants (fixed by the dataset)
#define LQ_   256
#define HH_   2
#define HQ_   32
#define DD_   128
#define SS_   16
#define BS_   64
#define GG_   16
#define NB_   64                           // Lkv / BS
#define SM_SCALE 0.08838834764831845f      // 1/sqrt(128)

// Packed KV scratch: fragment-native float2 pairs.
// kpack[h][nb][ub:8][kt:16][p:4][ul:8]  .x=K[ub*8+ul][kt*8+p]  .y=.. p+4
// vpack[h][nb][db:16][kt:8][p:4][dl:8]  .x=V[kt*8+p][db*8+dl]  .y=.. p+4
__device__ float2 g_kpack[HH_ * NB_ * 4096];
__device__ float2 g_vpack[HH_ * NB_ * 4096];

// Shared memory (float offsets)
#define QS_OFF   0
#define QS_STR   132                       // 16 rows x 132 (pitch !≡ 0 mod 128B)
#define PS_OFF   (QS_OFF + 16*132)         // 2112 ; double-buffered: 2 x 16 x 68
#define PS_STR   68
#define WS_OFF   (PS_OFF + 2*16*68)        // 4288
#define IDX_OFF  (WS_OFF + 256)            // 4544
#define SMEM_FLOATS (IDX_OFF + 16)
#define SMEM_BYTES  (SMEM_FLOATS * 4)      // 18,240 B

__device__ __forceinline__ unsigned smem_u32(const void* p) {
    return (unsigned)__cvta_generic_to_shared(p);
}

__device__ __forceinline__ void ldsm_x4(unsigned& r0, unsigned& r1,
                                        unsigned& r2, unsigned& r3, unsigned addr) {
    asm volatile("ldmatrix.sync.aligned.m8n8.x4.shared.b16 {%0,%1,%2,%3}, [%4];"
                 : "=r"(r0), "=r"(r1), "=r"(r2), "=r"(r3) : "r"(addr));
}

__device__ __forceinline__ void mma_tf32(float c[4],
                                         unsigned a0, unsigned a1, unsigned a2, unsigned a3,
                                         unsigned b0, unsigned b1) {
    asm volatile("mma.sync.aligned.m16n8k8.row.col.f32.tf32.tf32.f32 "
                 "{%0,%1,%2,%3}, {%4,%5,%6,%7}, {%8,%9}, {%0,%1,%2,%3};"
                 : "+f"(c[0]), "+f"(c[1]), "+f"(c[2]), "+f"(c[3])
                 : "r"(a0), "r"(a1), "r"(a2), "r"(a3), "r"(b0), "r"(b1));
}

__device__ __forceinline__ unsigned tf32_hi(unsigned x) {
    unsigned r;
    asm("cvt.rna.tf32.f32 %0, %1;" : "=r"(r) : "r"(x));
    return r;
}
__device__ __forceinline__ unsigned f_lo(unsigned x, unsigned hi) {
    return __float_as_uint(__fsub_rn(__uint_as_float(x), __uint_as_float(hi)));
}
#define SPLIT1(x)  unsigned x##h = tf32_hi(x), x##l = f_lo(x, x##h)
#define SPLITF(x)  unsigned x##h = tf32_hi(__float_as_uint(x)), \
                            x##l = f_lo(__float_as_uint(x), x##h)

// ---------------------------------------------------------------------------
// Prepass: pack K and V into fragment-native float2 tiles (one per kv block).
// ---------------------------------------------------------------------------
__global__ void __launch_bounds__(128)
pack_kv_kernel(const float* __restrict__ k, const float* __restrict__ v)
{
    const int nb = blockIdx.x, h = blockIdx.y;
    const float* kb = k + ((size_t)nb * BS_ * HH_ + h) * DD_;
    const float* vb = v + ((size_t)nb * BS_ * HH_ + h) * DD_;
    float2* kout = g_kpack + ((size_t)h * NB_ + nb) * 4096;
    float2* vout = g_vpack + ((size_t)h * NB_ + nb) * 4096;

    // K: pos = ((ub*16 + kt)*4 + p)*8 + ul
    for (int pos = threadIdx.x; pos < 4096; pos += 128) {
        int ul = pos & 7, p = (pos >> 3) & 3, kt = (pos >> 5) & 15, ub = pos >> 9;
        int u = ub * 8 + ul, d = kt * 8 + p;
        kout[pos] = make_float2(kb[(size_t)u * (HH_ * DD_) + d],
                                kb[(size_t)u * (HH_ * DD_) + d + 4]);
    }
    // V: pos = ((db*8 + kt)*4 + p)*8 + dl
    for (int pos = threadIdx.x; pos < 4096; pos += 128) {
        int dl = pos & 7, p = (pos >> 3) & 3, kt = (pos >> 5) & 7, db = pos >> 8;
        int d = db * 8 + dl, u = kt * 8 + p;
        vout[pos] = make_float2(vb[(size_t)u * (HH_ * DD_) + d],
                                vb[(size_t)(u + 4) * (HH_ * DD_) + d]);
    }
}

// ---------------------------------------------------------------------------
// Main kernel
// ---------------------------------------------------------------------------
__global__ void __launch_bounds__(128, 4)
hsa_prefill_kernel(const float* __restrict__ q, const float* __restrict__ w,
                   const int* __restrict__ bi, float* __restrict__ out)
{
    extern __shared__ float sm[];
    const int lq   = blockIdx.x;
    const int h    = blockIdx.y;
    const int tid  = threadIdx.x;
    const int warp = tid >> 5;
    const int lane = tid & 31;
    const int gID  = lane >> 2;   // 0..7
    const int tig  = lane & 3;    // 0..3

    // ---- Load Q tile [16][128], w coefs, block indices
    {
        const float* qb = q + ((size_t)lq * HQ_ + (size_t)h * GG_) * DD_;
        #pragma unroll
        for (int i = tid; i < (GG_ * DD_) / 4; i += 128) {
            int idx = i * 4;
            int g = idx >> 7, d = idx & 127;
            float4 val = *(const float4*)(qb + idx);
            *(float4*)(sm + QS_OFF + g * QS_STR + d) = val;
        }
        const float* wb = w + ((size_t)lq * HQ_ + (size_t)h * GG_) * SS_;
        for (int i = tid; i < GG_ * SS_; i += 128) sm[WS_OFF + i] = wb[i];
        if (tid < SS_)
            ((int*)(sm + IDX_OFF))[tid] = bi[((size_t)lq * HH_ + h) * SS_ + tid];
    }
    __syncthreads();

    // Persistent O accumulators (hi + correction kept separate -> 2x ILP)
    float oh[4][4], oc[4][4];
    #pragma unroll
    for (int i = 0; i < 4; i++)
        #pragma unroll
        for (int j = 0; j < 4; j++) { oh[i][j] = 0.f; oc[i][j] = 0.f; }

    // ldmatrix A-fragment address components
    const int lr = lane & 7;
    const int lt = lane >> 3;
    const int a_row = lr + ((lt & 1) << 3);
    const int a_col = (lt >> 1) << 2;

    // Per-lane packed-tile offsets (float2 units)
    const int lane_off = tig * 8 + gID;
    const float2* kp_base = g_kpack + (size_t)h * NB_ * 4096
                          + (warp * 2) * 512 + lane_off;       // + blk*4096 later
    const float2* vp_base = g_vpack + (size_t)h * NB_ * 4096
                          + (warp * 4) * 256 + lane_off;       // + blk*4096 later

    for (int s = 0; s < SS_; s++) {
        const int blk = ((const int*)(sm + IDX_OFF))[s];   // uniform across CTA
        float* ps = sm + PS_OFF + (s & 1) * (16 * PS_STR); // double-buffered P

        if (blk >= 0) {
            const float2* kp = kp_base + (size_t)blk * 4096;

            // ---- Scores S[16][64] = Q @ K^T (3xTF32)
            float cm[2][4] = {{0.f,0.f,0.f,0.f},{0.f,0.f,0.f,0.f}};
            float cc[2][4] = {{0.f,0.f,0.f,0.f},{0.f,0.f,0.f,0.f}};
            #pragma unroll
            for (int kt = 0; kt < 16; kt++) {
                unsigned a0, a1, a2, a3;
                ldsm_x4(a0, a1, a2, a3,
                        smem_u32(sm + QS_OFF + a_row * QS_STR + a_col + kt * 8));
                SPLIT1(a0); SPLIT1(a1); SPLIT1(a2); SPLIT1(a3);
                float2 k0 = kp[kt * 32];          // n-tile u0 = warp*16
                float2 k1 = kp[512 + kt * 32];    // n-tile u0 = warp*16 + 8
                float f0 = k0.x, f1 = k0.y, f2 = k1.x, f3 = k1.y;
                SPLITF(f0); SPLITF(f1); SPLITF(f2); SPLITF(f3);
                mma_tf32(cm[0], a0h, a1h, a2h, a3h, f0h, f1h);
                mma_tf32(cc[0], a0h, a1h, a2h, a3h, f0l, f1l);
                mma_tf32(cc[0], a0l, a1l, a2l, a3l, f0h, f1h);
                mma_tf32(cm[1], a0h, a1h, a2h, a3h, f2h, f3h);
                mma_tf32(cc[1], a0h, a1h, a2h, a3h, f2l, f3l);
                mma_tf32(cc[1], a0l, a1l, a2l, a3l, f2h, f3h);
            }
            // Spill scaled scores for the cross-warp softmax
            #pragma unroll
            for (int nt = 0; nt < 2; nt++) {
                const int u = (warp * 2 + nt) * 8 + tig * 2;
                *(float2*)(ps + gID * PS_STR + u) =
                    make_float2((cm[nt][0] + cc[nt][0]) * SM_SCALE,
                                (cm[nt][1] + cc[nt][1]) * SM_SCALE);
                *(float2*)(ps + (gID + 8) * PS_STR + u) =
                    make_float2((cm[nt][2] + cc[nt][2]) * SM_SCALE,
                                (cm[nt][3] + cc[nt][3]) * SM_SCALE);
            }
            __syncthreads();

            // ---- Per-(g, block) softmax over 64 keys; fold in w[g][s]/sum.
            {
                const int g = tid >> 3, j = tid & 7;
                float vals[8];
                #pragma unroll
                for (int m = 0; m < 8; m++) vals[m] = ps[g * PS_STR + j + m * 8];
                float mx = vals[0];
                #pragma unroll
                for (int m = 1; m < 8; m++) mx = fmaxf(mx, vals[m]);
                mx = fmaxf(mx, __shfl_xor_sync(0xffffffffu, mx, 1));
                mx = fmaxf(mx, __shfl_xor_sync(0xffffffffu, mx, 2));
                mx = fmaxf(mx, __shfl_xor_sync(0xffffffffu, mx, 4));
                float sum = 0.f;
                #pragma unroll
                for (int m = 0; m < 8; m++) { vals[m] = __expf(vals[m] - mx); sum += vals[m]; }
                sum += __shfl_xor_sync(0xffffffffu, sum, 1);
                sum += __shfl_xor_sync(0xffffffffu, sum, 2);
                sum += __shfl_xor_sync(0xffffffffu, sum, 4);
                const float coef = sm[WS_OFF + g * SS_ + s] / sum;
                #pragma unroll
                for (int m = 0; m < 8; m++)
                    ps[g * PS_STR + j + m * 8] = vals[m] * coef;
            }
            __syncthreads();

            // ---- O[16][128] += P[16][64] @ V[64][128] (3xTF32)
            const float2* vp = vp_base + (size_t)blk * 4096;
            #pragma unroll
            for (int kt = 0; kt < 8; kt++) {
                unsigned a0, a1, a2, a3;
                ldsm_x4(a0, a1, a2, a3,
                        smem_u32(ps + a_row * PS_STR + a_col + kt * 8));
                SPLIT1(a0); SPLIT1(a1); SPLIT1(a2); SPLIT1(a3);
                #pragma unroll
                for (int nt = 0; nt < 4; nt++) {
                    float2 vv = vp[nt * 256 + kt * 32];
                    float f0 = vv.x, f1 = vv.y;
                    SPLITF(f0); SPLITF(f1);
                    mma_tf32(oh[nt], a0h, a1h, a2h, a3h, f0h, f1h);
                    mma_tf32(oc[nt], a0h, a1h, a2h, a3h, f0l, f1l);
                    mma_tf32(oc[nt], a0l, a1l, a2l, a3l, f0h, f1h);
                }
            }
            // No end barrier: next iteration spills into the OTHER P buffer;
            // its pre-softmax barrier orders everything else.
        }
    }

    // ---- Write O: warp's d-slice, fragment rows gID / gID+8.
    float* ob = out + ((size_t)lq * HQ_ + (size_t)h * GG_) * DD_;
    #pragma unroll
    for (int nt = 0; nt < 4; nt++) {
        const int d = warp * 32 + nt * 8 + tig * 2;
        *(float2*)(ob + (size_t)gID * DD_ + d) =
            make_float2(oh[nt][0] + oc[nt][0], oh[nt][1] + oc[nt][1]);
        *(float2*)(ob + (size_t)(gID + 8) * DD_ + d) =
            make_float2(oh[nt][2] + oc[nt][2], oh[nt][3] + oc[nt][3]);
    }
}

extern "C" void kernel_launch(void* const* d_in, const int* in_sizes, int n_in,
                              void* d_out, int out_size)
{
    const float* q  = (const float*)d_in[0];
    const float* k  = (const float*)d_in[1];
    const float* v  = (const float*)d_in[2];
    const float* w  = (const float*)d_in[3];
    const int*   bi = (const int*)d_in[4];
    float* out = (float*)d_out;

    pack_kv_kernel<<<dim3(NB_, HH_), 128>>>(k, v);

    cudaFuncSetAttribute(hsa_prefill_kernel,
                         cudaFuncAttributeMaxDynamicSharedMemorySize, SMEM_BYTES);
    hsa_prefill_kernel<<<dim3(LQ_, HH_), 128, SMEM_BYTES>>>(q, w, bi, out);
}